// round 15
// baseline (speedup 1.0000x reference)
#include <cuda_runtime.h>
#include <cuda_bf16.h>
#include <cuda_fp16.h>
#include <cstdint>

// ---------------- constants ----------------
#define BB 64
#define C_IN 256
#define CH 128
#define NPH 64
#define SP 256          // R*R spatial
#define ED 128
#define NE 1024
#define C_OUT 256
#define FLAT_PH 16384   // NPH*R*R
#define FLAT_Z 4096     // ED*CB*NL
#define NROWS 2048      // B*CB*NL
#define OUT_ELEMS (BB*C_OUT*SP)   // 4194304

typedef unsigned long long u64;
typedef unsigned int u32;

#define DINLINE __device__ __forceinline__

DINLINE u64 pack2(float lo, float hi){ u64 r; asm("mov.b64 %0, {%1,%2};" : "=l"(r) : "f"(lo), "f"(hi)); return r; }
DINLINE void unpack2(u64 v, float &lo, float &hi){ asm("mov.b64 {%0,%1}, %2;" : "=f"(lo), "=f"(hi) : "l"(v)); }
DINLINE u64 fma2(u64 a, u64 b, u64 c){ u64 d; asm("fma.rn.f32x2 %0, %1, %2, %3;" : "=l"(d) : "l"(a), "l"(b), "l"(c)); return d; }
DINLINE float silu_f(float x){ return x / (1.f + __expf(-x)); }

// ---- fast bf16 split: h = bf16x2(x,y), l = bf16x2(residuals); 6 instrs ----
DINLINE void split2(float x, float y, u32 &h, u32 &l){
    asm("cvt.rn.bf16x2.f32 %0, %1, %2;" : "=r"(h) : "f"(y), "f"(x));   // hi=y, lo=x
    float xh = __uint_as_float(h << 16);
    float yh = __uint_as_float(h & 0xFFFF0000u);
    float rx = x - xh, ry = y - yh;
    asm("cvt.rn.bf16x2.f32 %0, %1, %2;" : "=r"(l) : "f"(ry), "f"(rx));
}

// ---- fp16 pack / split ----
DINLINE u32 packh(float x, float y){
    u32 r; asm("cvt.rn.f16x2.f32 %0, %1, %2;" : "=r"(r) : "f"(y), "f"(x)); return r;
}
DINLINE void split2h(float x, float y, u32 &h, u32 &l){
    h = packh(x, y);
    float xh, yh;
    asm("{.reg .b16 lo, hi; mov.b32 {lo, hi}, %2; cvt.f32.f16 %0, lo; cvt.f32.f16 %1, hi;}"
        : "=f"(xh), "=f"(yh) : "r"(h));
    l = packh(x - xh, y - yh);
}

DINLINE uint32_t smem_u32(const void* p){
    uint32_t a;
    asm("{ .reg .u64 t; cvta.to.shared.u64 t, %1; cvt.u32.u64 %0, t; }" : "=r"(a) : "l"(p));
    return a;
}
DINLINE void sts64(uint32_t addr, u32 a, u32 b){
    asm volatile("st.shared.v2.b32 [%0], {%1,%2};" :: "r"(addr), "r"(a), "r"(b) : "memory");
}
DINLINE void sts128q(uint32_t addr, u32 a, u32 b, u32 c, u32 d){
    asm volatile("st.shared.v4.b32 [%0], {%1,%2,%3,%4};" :: "r"(addr), "r"(a), "r"(b), "r"(c), "r"(d) : "memory");
}
DINLINE u32 lds32(uint32_t addr){
    u32 v; asm volatile("ld.shared.b32 %0, [%1];" : "=r"(v) : "r"(addr)); return v;
}
DINLINE void ldsm4(u32 (&r)[4], uint32_t addr){
    asm volatile("ldmatrix.sync.aligned.m8n8.x4.shared.b16 {%0,%1,%2,%3}, [%4];"
                 : "=r"(r[0]), "=r"(r[1]), "=r"(r[2]), "=r"(r[3]) : "r"(addr));
}
DINLINE void mma_bf16(float (&d)[4], const u32 (&a)[4], const u32 (&b)[2]){
    asm volatile("mma.sync.aligned.m16n8k16.row.col.f32.bf16.bf16.f32 "
                 "{%0,%1,%2,%3}, {%4,%5,%6,%7}, {%8,%9}, {%0,%1,%2,%3};"
                 : "+f"(d[0]), "+f"(d[1]), "+f"(d[2]), "+f"(d[3])
                 : "r"(a[0]), "r"(a[1]), "r"(a[2]), "r"(a[3]), "r"(b[0]), "r"(b[1]));
}
DINLINE void mma_f16(float (&d)[4], const u32 (&a)[4], const u32 (&b)[2]){
    asm volatile("mma.sync.aligned.m16n8k16.row.col.f32.f16.f16.f32 "
                 "{%0,%1,%2,%3}, {%4,%5,%6,%7}, {%8,%9}, {%0,%1,%2,%3};"
                 : "+f"(d[0]), "+f"(d[1]), "+f"(d[2]), "+f"(d[3])
                 : "r"(a[0]), "r"(a[1]), "r"(a[2]), "r"(a[3]), "r"(b[0]), "r"(b[1]));
}
DINLINE void cp_async16(uint32_t dst, const void* src){
    asm volatile("cp.async.cg.shared.global [%0], [%1], 16;" :: "r"(dst), "l"(src) : "memory");
}
#define CP_COMMIT() asm volatile("cp.async.commit_group;" ::: "memory")
#define CP_WAIT0()  asm volatile("cp.async.wait_group 0;" ::: "memory")

// ---- mbarrier helpers (sm_80+ PTX; compiles on compute_103) ----
DINLINE void mbar_init(uint32_t mbar, uint32_t cnt){
    asm volatile("mbarrier.init.shared.b64 [%0], %1;" :: "r"(mbar), "r"(cnt) : "memory");
}
DINLINE void mbar_arrive(uint32_t mbar){
    asm volatile("mbarrier.arrive.shared.b64 _, [%0];" :: "r"(mbar) : "memory");
}
DINLINE void mbar_wait(uint32_t mbar, uint32_t phase){
    asm volatile(
        "{\n\t.reg .pred P;\n\t"
        "LW%=:\n\t"
        "mbarrier.try_wait.parity.shared.b64 P, [%0], %1;\n\t"
        "@P bra LD%=;\n\t"
        "bra LW%=;\n\t"
        "LD%=:\n\t}"
        :: "r"(mbar), "r"(phase) : "memory");
}

// ---------------- scratch (device globals; no allocs) ----------------
__device__ float g_hphylo[BB*FLAT_PH];   // conv_in phylo half (pre-LN)
__device__ float g_himg  [BB*FLAT_PH];   // conv_in img half (raw)
__device__ float g_stats [BB*2];         // mu, rstd per batch
__device__ float g_zp    [8*BB*FLAT_Z];  // split-K partials (8MB, shared by both MLPs)
__device__ float g_z     [BB*FLAT_Z];    // z
__device__ float g_zq    [BB*FLAT_Z];    // quantized z (fp32)
__device__ float g_hout  [BB*FLAT_PH];   // mlp_out output
__device__ float g_cnorm [NE];           // |codebook_e|^2
__device__ u64   g_key   [NROWS];        // packed (sortable_dist<<32)|idx
__device__ float g_losspart[NROWS];
// packed activations: word w at [k2][batch]
__device__ u32   g_aph[(FLAT_PH/2)*BB];  // hn bf16 hi
__device__ u32   g_apl[(FLAT_PH/2)*BB];  // hn bf16 lo
__device__ u32   g_zpk[(FLAT_Z/2)*BB];   // zq fp16x2 (single precision term)

// ---------------- layernorm stats ----------------
__global__ void __launch_bounds__(256) ln_stats_k()
{
    int b = blockIdx.x;
    const float4* p = (const float4*)(g_hphylo + b*FLAT_PH);
    float s = 0.f, s2 = 0.f;
    for (int i = threadIdx.x; i < FLAT_PH/4; i += 256){
        float4 v = p[i];
        s  += v.x + v.y + v.z + v.w;
        s2 += v.x*v.x + v.y*v.y + v.z*v.z + v.w*v.w;
    }
    __shared__ float rs[256], rq[256];
    rs[threadIdx.x] = s; rq[threadIdx.x] = s2;
    __syncthreads();
    for (int off = 128; off; off >>= 1){
        if (threadIdx.x < off){ rs[threadIdx.x]+=rs[threadIdx.x+off]; rq[threadIdx.x]+=rq[threadIdx.x+off]; }
        __syncthreads();
    }
    if (threadIdx.x == 0){
        float mu = rs[0] * (1.f/FLAT_PH);
        float var = rq[0] * (1.f/FLAT_PH) - mu*mu;
        g_stats[b*2+0] = mu;
        g_stats[b*2+1] = rsqrtf(var + 1e-5f);
    }
}

// layernorm apply + bf16 hi/lo pack -> g_aph/g_apl ([k2][batch] layout)
__global__ void __launch_bounds__(256) ln_norm_k(const float* __restrict__ lnw,
                                                 const float* __restrict__ lnb)
{
    int b = blockIdx.x;
    int base = blockIdx.y * 1024 + threadIdx.x * 4;
    float mu = g_stats[b*2+0], rstd = g_stats[b*2+1];
    float4 v = *(const float4*)(g_hphylo + b*FLAT_PH + base);
    float4 w = *(const float4*)(lnw + base);
    float4 bb = *(const float4*)(lnb + base);
    float o0 = (v.x-mu)*rstd*w.x + bb.x;
    float o1 = (v.y-mu)*rstd*w.y + bb.y;
    float o2 = (v.z-mu)*rstd*w.z + bb.z;
    float o3 = (v.w-mu)*rstd*w.w + bb.w;
    u32 h0,l0,h1,l1;
    split2(o0,o1,h0,l0);
    split2(o2,o3,h1,l1);
    int k2 = base >> 1;
    g_aph[(size_t)k2*BB + b]     = h0;
    g_aph[(size_t)(k2+1)*BB + b] = h1;
    g_apl[(size_t)k2*BB + b]     = l0;
    g_apl[(size_t)(k2+1)*BB + b] = l1;
}

// ================= warp-specialized bf16x3 MLP GEMM (mlp_in) =================
// 8 consumer warps (MMA) + 4 producer warps (W LDG->split->STS, A cp.async).
// 3-stage ring with full/empty mbarriers; no __syncthreads in mainloop.
// stage layout: Wh[128][40]b16 @0 | Wl @10240 | Ah[16][72]u32 @20480 | Al @25088; stage=29696
#define MMA_BUF 29696
#define NSTAGE 3
#define WS_SMEM (NSTAGE*MMA_BUF + 64)

__global__ void __launch_bounds__(384)
mlp_mma_ws_k(const u32* __restrict__ Aph, const u32* __restrict__ Apl,
             const float* __restrict__ W, float* __restrict__ C,
             int K, int N, int kchunk)
{
    extern __shared__ char dsm[];
    uint32_t sb = smem_u32(dsm);
    uint32_t barb = sb + NSTAGE*MMA_BUF;

    int tid = threadIdx.x;
    int lane = tid & 31, wid = tid >> 5;
    int jbase = blockIdx.x * 128;
    int k0 = blockIdx.y * kchunk;
    float* Cout = C + (size_t)blockIdx.y * 64 * N;
    const int nch = kchunk >> 5;

    if (tid == 0){
        #pragma unroll
        for (int s = 0; s < NSTAGE; s++){
            mbar_init(barb + s*16, 128);       // full: 128 producer threads arrive
            mbar_init(barb + s*16 + 8, 256);   // empty: 256 consumer threads arrive
        }
    }
    __syncthreads();

    if (wid >= 8){
        // ---------------- producer (128 threads) ----------------
        int ptid = tid - 256;
        float4 wreg[8];
        #pragma unroll
        for (int i=0;i<8;i++){ int idx=ptid+128*i; int r=idx>>3, s8=idx&7;
            wreg[i] = *(const float4*)(W + (size_t)(jbase+r)*K + k0 + s8*4); }

        int s = 0, w = 0;
        for (int ch = 0; ch < nch; ch++){
            // split current W (register work; overlaps nothing blocking)
            u32 wsh[16], wsl[16];
            #pragma unroll
            for (int i=0;i<8;i++){
                split2(wreg[i].x, wreg[i].y, wsh[2*i],   wsl[2*i]);
                split2(wreg[i].z, wreg[i].w, wsh[2*i+1], wsl[2*i+1]);
            }
            // prefetch next chunk's W (LDG latency overlaps wait+STS below)
            if (ch+1 < nch){
                int kk = k0 + (ch+1)*32;
                #pragma unroll
                for (int i=0;i<8;i++){ int idx=ptid+128*i; int r=idx>>3, s8=idx&7;
                    wreg[i] = *(const float4*)(W + (size_t)(jbase+r)*K + kk + s8*4); }
            }
            if (ch >= NSTAGE) mbar_wait(barb + s*16 + 8, (w-1)&1);
            uint32_t st = sb + s*MMA_BUF;
            int kbase = (k0 + ch*32) >> 1;
            #pragma unroll
            for (int i=0;i<2;i++){ int o=ptid+128*i; int k2=o>>4, b4=(o&15)*4;
                uint32_t ao = (u32)(k2*72 + b4)*4;
                cp_async16(st + 20480 + ao, Aph + (size_t)(kbase+k2)*BB + b4);
                cp_async16(st + 25088 + ao, Apl + (size_t)(kbase+k2)*BB + b4);
            }
            CP_COMMIT();
            #pragma unroll
            for (int i=0;i<8;i++){ int idx=ptid+128*i; int r=idx>>3, s8=idx&7;
                uint32_t off = r*80 + s8*8;
                sts64(st + off,         wsh[2*i], wsh[2*i+1]);
                sts64(st + 10240 + off, wsl[2*i], wsl[2*i+1]);
            }
            CP_WAIT0();
            mbar_arrive(barb + s*16);
            s++; if (s == NSTAGE){ s = 0; w++; }
        }
    } else {
        // ---------------- consumer (256 threads, 8 warps) ----------------
        int g = lane >> 2, tig = lane & 3;
        int jw = (wid & 3) * 32, bw = (wid >> 2) * 32;
        int lrow = ((lane>>3)&1)*8 + (lane&7);
        int lkc  = (lane>>4)*8;

        float dacc[2][4][4];
        #pragma unroll
        for (int m=0;m<2;m++)
            #pragma unroll
            for (int n=0;n<4;n++)
                #pragma unroll
                for (int q=0;q<4;q++) dacc[m][n][q] = 0.f;

        int s = 0, pf = 0;
        for (int ch = 0; ch < nch; ch++){
            mbar_wait(barb + s*16, pf);
            uint32_t Bb = sb + s*MMA_BUF;
            #pragma unroll
            for (int ks = 0; ks < 2; ks++){
                u32 wh[2][4], wl[2][4];
                #pragma unroll
                for (int m=0;m<2;m++){
                    uint32_t ad = Bb + (u32)((jw + m*16 + lrow)*40 + lkc + ks*16)*2;
                    ldsm4(wh[m], ad);
                    ldsm4(wl[m], ad + 10240);
                }
                u32 bh[4][2], bl[4][2];
                #pragma unroll
                for (int nf=0;nf<4;nf++){
                    uint32_t a0 = Bb + 20480 + (u32)((ks*8+tig)*72 + bw + nf*8 + g)*4;
                    bh[nf][0] = lds32(a0);
                    bh[nf][1] = lds32(a0 + 4*72*4);
                    bl[nf][0] = lds32(a0 + 4608);
                    bl[nf][1] = lds32(a0 + 4608 + 4*72*4);
                }
                #pragma unroll
                for (int m=0;m<2;m++)
                    #pragma unroll
                    for (int nf=0;nf<4;nf++){
                        mma_bf16(dacc[m][nf], wh[m], bh[nf]);
                        mma_bf16(dacc[m][nf], wh[m], bl[nf]);
                        mma_bf16(dacc[m][nf], wl[m], bh[nf]);
                    }
            }
            mbar_arrive(barb + s*16 + 8);
            s++; if (s == NSTAGE){ s = 0; pf ^= 1; }
        }

        #pragma unroll
        for (int m=0;m<2;m++){
            int j = jbase + jw + m*16 + g;
            #pragma unroll
            for (int nf=0;nf<4;nf++){
                int b = bw + nf*8 + 2*tig;
                Cout[(size_t)b*N + j]         = dacc[m][nf][0];
                Cout[(size_t)(b+1)*N + j]     = dacc[m][nf][1];
                Cout[(size_t)b*N + j + 8]     = dacc[m][nf][2];
                Cout[(size_t)(b+1)*N + j + 8] = dacc[m][nf][3];
            }
        }
    }
}

// ---------------- mma.sync fp16x2 MLP GEMM (mlp_out; 2 passes, R13 config) ----------------
// smem: Wh[128][40]b16 @0 (10240) | Wl @10240 | A[16][72]u32 @20480 (4608); BUF2=25088
#define MMA2_BUF 25088
#define MMA2_SMEM (2*MMA2_BUF)

__global__ void __launch_bounds__(256, 2)
mlp_mma2_k(const u32* __restrict__ Apk,
           const float* __restrict__ W, float* __restrict__ C,
           int K, int N, int kchunk)
{
    extern __shared__ char dsm[];
    uint32_t sb = smem_u32(dsm);

    int tid = threadIdx.x;
    int lane = tid & 31, wid = tid >> 5;
    int g = lane >> 2, tig = lane & 3;
    int jw = (wid & 3) * 32, bw = (wid >> 2) * 32;
    int jbase = blockIdx.x * 128;
    int k0 = blockIdx.y * kchunk;
    float* Cout = C + (size_t)blockIdx.y * 64 * N;

    float dacc[2][4][4];
    #pragma unroll
    for (int m=0;m<2;m++)
        #pragma unroll
        for (int n=0;n<4;n++)
            #pragma unroll
            for (int q=0;q<4;q++) dacc[m][n][q] = 0.f;

    const int nch = kchunk >> 5;
    int k2t = tid >> 4, b4 = (tid & 15) * 4;
    uint32_t aoff = (u32)(k2t*72 + b4)*4;

    float4 wreg[4];

    {
        int kbase = k0 >> 1;
        cp_async16(sb + 20480 + aoff, Apk + (size_t)(kbase + k2t)*BB + b4);
        CP_COMMIT();
    }
    #pragma unroll
    for (int i=0;i<4;i++){ int idx=tid+256*i; int r=idx>>3, s=idx&7;
        wreg[i] = *(const float4*)(W + (size_t)(jbase+r)*K + k0 + s*4); }
    #pragma unroll
    for (int i=0;i<4;i++){ int idx=tid+256*i; int r=idx>>3, s=idx&7;
        u32 h0,l0,h1,l1;
        split2h(wreg[i].x, wreg[i].y, h0, l0);
        split2h(wreg[i].z, wreg[i].w, h1, l1);
        uint32_t off = r*80 + s*8;
        sts64(sb + off, h0, h1);
        sts64(sb + 10240 + off, l0, l1);
    }
    CP_WAIT0();
    __syncthreads();

    for (int ch = 0; ch < nch; ch++){
        int cur = ch & 1;
        bool more = (ch+1) < nch;
        if (more){
            int kk = k0 + (ch+1)*32;
            uint32_t Bn = sb + (cur^1)*MMA2_BUF;
            int kbase = kk >> 1;
            cp_async16(Bn + 20480 + aoff, Apk + (size_t)(kbase + k2t)*BB + b4);
            CP_COMMIT();
            #pragma unroll
            for (int i=0;i<4;i++){ int idx=tid+256*i; int r=idx>>3, s=idx&7;
                wreg[i] = *(const float4*)(W + (size_t)(jbase+r)*K + kk + s*4); }
        }

        {
            uint32_t Bb = sb + cur*MMA2_BUF;
            int lrow = ((lane>>3)&1)*8 + (lane&7);
            int lkc  = (lane>>4)*8;
            #pragma unroll
            for (int ks = 0; ks < 2; ks++){
                u32 wh[2][4], wl[2][4];
                #pragma unroll
                for (int m=0;m<2;m++){
                    uint32_t ad = Bb + (u32)((jw + m*16 + lrow)*40 + lkc + ks*16)*2;
                    ldsm4(wh[m], ad);
                    ldsm4(wl[m], ad + 10240);
                }
                u32 bh[4][2];
                #pragma unroll
                for (int nf=0;nf<4;nf++){
                    uint32_t a0 = Bb + 20480 + (u32)((ks*8+tig)*72 + bw + nf*8 + g)*4;
                    bh[nf][0] = lds32(a0);
                    bh[nf][1] = lds32(a0 + 4*72*4);
                }
                #pragma unroll
                for (int m=0;m<2;m++)
                    #pragma unroll
                    for (int nf=0;nf<4;nf++){
                        mma_f16(dacc[m][nf], wh[m], bh[nf]);
                        mma_f16(dacc[m][nf], wl[m], bh[nf]);
                    }
            }
        }

        if (more){
            uint32_t Bn = sb + (cur^1)*MMA2_BUF;
            #pragma unroll
            for (int i=0;i<4;i++){ int idx=tid+256*i; int r=idx>>3, s=idx&7;
                u32 h0,l0,h1,l1;
                split2h(wreg[i].x, wreg[i].y, h0, l0);
                split2h(wreg[i].z, wreg[i].w, h1, l1);
                uint32_t off = r*80 + s*8;
                sts64(Bn + off, h0, h1);
                sts64(Bn + 10240 + off, l0, l1);
            }
        }
        CP_WAIT0();
        __syncthreads();
    }

    #pragma unroll
    for (int m=0;m<2;m++){
        int j = jbase + jw + m*16 + g;
        #pragma unroll
        for (int nf=0;nf<4;nf++){
            int b = bw + nf*8 + 2*tig;
            Cout[(size_t)b*N + j]         = dacc[m][nf][0];
            Cout[(size_t)(b+1)*N + j]     = dacc[m][nf][1];
            Cout[(size_t)b*N + j + 8]     = dacc[m][nf][2];
            Cout[(size_t)(b+1)*N + j + 8] = dacc[m][nf][3];
        }
    }
}

// ---------------- mma.sync bf16x3 CONV GEMM (unchanged, proven) ----------------
#define MMA_SMEM (2*MMA_BUF)

template<int EPI>
__global__ void __launch_bounds__(256, 2)
conv_mma_k(const float* __restrict__ src0, const float* __restrict__ src1,
           int csplit, int sb0, int sb1,
           const float* __restrict__ W, const float* __restrict__ bias,
           float* __restrict__ out, int K)
{
    extern __shared__ char dsm[];
    uint32_t sb = smem_u32(dsm);

    int tid = threadIdx.x;
    int lane = tid & 31, wid = tid >> 5;
    int g = lane >> 2, tig = lane & 3;
    int jw = (wid & 3) * 32, bw = (wid >> 2) * 32;
    int jbase = blockIdx.y * 128;
    int nbase = blockIdx.x * 64;
    int b = nbase >> 8, pbase = nbase & 255;

    float dacc[2][4][4];
    #pragma unroll
    for (int m=0;m<2;m++)
        #pragma unroll
        for (int n=0;n<4;n++)
            #pragma unroll
            for (int q=0;q<4;q++) dacc[m][n][q] = 0.f;

    const int nch = K >> 5;
    int c2t = tid >> 4, p4 = tid & 15;

    float4 wreg[4], bf0, bf1;

    #pragma unroll
    for (int i=0;i<4;i++){ int idx=tid+256*i; int r=idx>>3, s=idx&7;
        wreg[i] = *(const float4*)(W + (size_t)(jbase+r)*K + s*4); }
    {
        int c = 2*c2t;
        const float* s0 = (c < csplit) ? (src0 + (size_t)b*sb0 + c*256)
                                       : (src1 + (size_t)b*sb1 + (c-csplit)*256);
        bf0 = *(const float4*)(s0 + pbase + p4*4);
        bf1 = *(const float4*)(s0 + 256 + pbase + p4*4);
    }
    {
        uint32_t Bb = sb;
        #pragma unroll
        for (int i=0;i<4;i++){ int idx=tid+256*i; int r=idx>>3, s=idx&7;
            u32 h0,l0,h1,l1;
            split2(wreg[i].x, wreg[i].y, h0, l0);
            split2(wreg[i].z, wreg[i].w, h1, l1);
            uint32_t off = r*80 + s*8;
            sts64(Bb + off, h0, h1);
            sts64(Bb + 10240 + off, l0, l1);
        }
        u32 h[4], l[4];
        split2(silu_f(bf0.x), silu_f(bf1.x), h[0], l[0]);
        split2(silu_f(bf0.y), silu_f(bf1.y), h[1], l[1]);
        split2(silu_f(bf0.z), silu_f(bf1.z), h[2], l[2]);
        split2(silu_f(bf0.w), silu_f(bf1.w), h[3], l[3]);
        uint32_t off = (u32)(c2t*72 + p4*4)*4;
        sts128q(Bb + 20480 + off, h[0], h[1], h[2], h[3]);
        sts128q(Bb + 25088 + off, l[0], l[1], l[2], l[3]);
    }
    __syncthreads();

    for (int ch = 0; ch < nch; ch++){
        int cur = ch & 1;
        bool more = (ch+1) < nch;
        if (more){
            int kk = (ch+1)*32;
            #pragma unroll
            for (int i=0;i<4;i++){ int idx=tid+256*i; int r=idx>>3, s=idx&7;
                wreg[i] = *(const float4*)(W + (size_t)(jbase+r)*K + kk + s*4); }
            int c = kk + 2*c2t;
            const float* s0 = (c < csplit) ? (src0 + (size_t)b*sb0 + c*256)
                                           : (src1 + (size_t)b*sb1 + (c-csplit)*256);
            bf0 = *(const float4*)(s0 + pbase + p4*4);
            bf1 = *(const float4*)(s0 + 256 + pbase + p4*4);
        }

        {
            uint32_t Bb = sb + cur*MMA_BUF;
            int lrow = ((lane>>3)&1)*8 + (lane&7);
            int lkc  = (lane>>4)*8;
            #pragma unroll
            for (int ks = 0; ks < 2; ks++){
                u32 wh[2][4], wl[2][4];
                #pragma unroll
                for (int m=0;m<2;m++){
                    uint32_t ad = Bb + (u32)((jw + m*16 + lrow)*40 + lkc + ks*16)*2;
                    ldsm4(wh[m], ad);
                    ldsm4(wl[m], ad + 10240);
                }
                u32 bh[4][2], bl[4][2];
                #pragma unroll
                for (int nf=0;nf<4;nf++){
                    uint32_t a0 = Bb + 20480 + (u32)((ks*8+tig)*72 + bw + nf*8 + g)*4;
                    bh[nf][0] = lds32(a0);
                    bh[nf][1] = lds32(a0 + 4*72*4);
                    bl[nf][0] = lds32(a0 + 4608);
                    bl[nf][1] = lds32(a0 + 4608 + 4*72*4);
                }
                #pragma unroll
                for (int m=0;m<2;m++)
                    #pragma unroll
                    for (int nf=0;nf<4;nf++){
                        mma_bf16(dacc[m][nf], wh[m], bh[nf]);
                        mma_bf16(dacc[m][nf], wh[m], bl[nf]);
                        mma_bf16(dacc[m][nf], wl[m], bh[nf]);
                    }
            }
        }

        if (more){
            uint32_t Bb = sb + (cur^1)*MMA_BUF;
            #pragma unroll
            for (int i=0;i<4;i++){ int idx=tid+256*i; int r=idx>>3, s=idx&7;
                u32 h0,l0,h1,l1;
                split2(wreg[i].x, wreg[i].y, h0, l0);
                split2(wreg[i].z, wreg[i].w, h1, l1);
                uint32_t off = r*80 + s*8;
                sts64(Bb + off, h0, h1);
                sts64(Bb + 10240 + off, l0, l1);
            }
            u32 h[4], l[4];
            split2(silu_f(bf0.x), silu_f(bf1.x), h[0], l[0]);
            split2(silu_f(bf0.y), silu_f(bf1.y), h[1], l[1]);
            split2(silu_f(bf0.z), silu_f(bf1.z), h[2], l[2]);
            split2(silu_f(bf0.w), silu_f(bf1.w), h[3], l[3]);
            uint32_t off = (u32)(c2t*72 + p4*4)*4;
            sts128q(Bb + 20480 + off, h[0], h[1], h[2], h[3]);
            sts128q(Bb + 25088 + off, l[0], l[1], l[2], l[3]);
        }
        __syncthreads();
    }

    #pragma unroll
    for (int m=0;m<2;m++){
        int j = jbase + jw + m*16 + g;
        float b0v = bias[j], b1v = bias[j+8];
        #pragma unroll
        for (int nf=0;nf<4;nf++){
            int p = pbase + bw + nf*8 + 2*tig;
            float v0 = dacc[m][nf][0] + b0v, v1 = dacc[m][nf][1] + b0v;
            float v2 = dacc[m][nf][2] + b1v, v3 = dacc[m][nf][3] + b1v;
            if (EPI == 1){
                float* d0 = (j < NPH) ? (g_hphylo + (size_t)b*FLAT_PH + j*256 + p)
                                      : (g_himg   + (size_t)b*FLAT_PH + (j-NPH)*256 + p);
                *(float2*)d0          = make_float2(v0, v1);
                *(float2*)(d0 + 2048) = make_float2(v2, v3);
            } else {
                float* d0 = out + (size_t)b*(C_OUT*SP) + (size_t)j*256 + p;
                *(float2*)d0          = make_float2(v0, v1);
                *(float2*)(d0 + 2048) = make_float2(v2, v3);
            }
        }
    }
}

// ---------------- combine nsplit partials + bias ----------------
__global__ void __launch_bounds__(256) combine_k(const float* __restrict__ P,
                                                 float* __restrict__ out,
                                                 const float* __restrict__ bias,
                                                 int nsplit, int total, int N)
{
    int i = blockIdx.x * 256 + threadIdx.x;
    const float4* P4 = (const float4*)P;
    float4 s = P4[i];
    int stride = total >> 2;
    for (int sp = 1; sp < nsplit; sp++){
        float4 a = P4[i + sp*stride];
        s.x+=a.x; s.y+=a.y; s.z+=a.z; s.w+=a.w;
    }
    int j = (i * 4) & (N - 1);
    float4 bv = *(const float4*)(bias + j);
    s.x+=bv.x; s.y+=bv.y; s.z+=bv.z; s.w+=bv.w;
    ((float4*)out)[i] = s;
}

// ---------------- codebook norms + vq init (fused) ----------------
__global__ void __launch_bounds__(256) cnorm_k(const float* __restrict__ cb)
{
    int e = blockIdx.x * 256 + threadIdx.x;      // 0..1023
    const float4* r = (const float4*)(cb + e*ED);
    float s = 0.f;
    #pragma unroll 8
    for (int i = 0; i < ED/4; i++){
        float4 v = r[i];
        s += v.x*v.x + v.y*v.y + v.z*v.z + v.w*v.w;
    }
    g_cnorm[e] = s;
    g_key[2*e]   = ~0ULL;
    g_key[2*e+1] = ~0ULL;
    g_losspart[2*e]   = 0.f;
    g_losspart[2*e+1] = 0.f;
}

// ---------------- VQ distance GEMM + argmin ----------------
__global__ void __launch_bounds__(256) vq_gemm_k(const float* __restrict__ cb)
{
    int rbase = blockIdx.x * 64;
    int ebase = blockIdx.y * 128;
    int b0 = rbase >> 5;

    __shared__ float Zs[32][68];
    __shared__ float Cs[32][132];
    __shared__ float cn[128];

    int tid = threadIdx.x;
    if (tid < 128) cn[tid] = g_cnorm[ebase + tid];
    int tx = tid & 15, ty = tid >> 4;
    int r0 = ty * 4, e0 = tx * 8;

    u64 acc2[4][4];
    #pragma unroll
    for (int i=0;i<4;i++)
        #pragma unroll
        for (int j=0;j<4;j++) acc2[i][j] = pack2(0.f,0.f);

    for (int kc = 0; kc < ED; kc += 32){
        #pragma unroll
        for (int it = 0; it < 2; it++){
            int i = tid + it*256;
            int brel = i >> 8;
            int t = (i & 255) * 4;
            float4 v = *(const float4*)(g_z + (b0+brel)*FLAT_Z + kc*32 + t);
            int k = t >> 5, s = t & 31;
            *(float4*)&Zs[k][brel*32 + s] = v;
        }
        #pragma unroll
        for (int it = 0; it < 4; it++){
            int i = tid + it*256;
            int el = i >> 3; int kq = (i & 7) * 4;
            float4 v = *(const float4*)(cb + (ebase+el)*ED + kc + kq);
            Cs[kq+0][el]=v.x; Cs[kq+1][el]=v.y; Cs[kq+2][el]=v.z; Cs[kq+3][el]=v.w;
        }
        __syncthreads();
        #pragma unroll 4
        for (int k = 0; k < 32; k++){
            float4 a  = *(const float4*)&Zs[k][r0];
            float4 c0 = *(const float4*)&Cs[k][e0];
            float4 c1 = *(const float4*)&Cs[k][e0+4];
            u64 cp[4] = {pack2(c0.x,c0.y), pack2(c0.z,c0.w),
                         pack2(c1.x,c1.y), pack2(c1.z,c1.w)};
            float av[4] = {a.x,a.y,a.z,a.w};
            #pragma unroll
            for (int i=0;i<4;i++){
                u64 aa = pack2(av[i], av[i]);
                #pragma unroll
                for (int j=0;j<4;j++) acc2[i][j] = fma2(aa, cp[j], acc2[i][j]);
            }
        }
        __syncthreads();
    }

    #pragma unroll
    for (int i=0;i<4;i++){
        float best = 3.4e38f; int be = 0;
        #pragma unroll
        for (int j=0;j<4;j++){
            float d0, d1;
            unpack2(acc2[i][j], d0, d1);
            float da = cn[e0+2*j]   - 2.f*d0;
            float db = cn[e0+2*j+1] - 2.f*d1;
            if (da < best){ best = da; be = e0+2*j; }
            if (db < best){ best = db; be = e0+2*j+1; }
        }
        unsigned int bits = __float_as_uint(best);
        unsigned int key32 = (bits & 0x80000000u) ? ~bits : (bits | 0x80000000u);
        u64 key = ((u64)key32 << 32) | (unsigned)(ebase + be);
        atomicMin(&g_key[rbase + r0 + i], key);
    }
}

// ---------------- gather zq (fp32) + per-row loss partial ----------------
__global__ void __launch_bounds__(128) vq_gather_k(const float* __restrict__ cb)
{
    int r = blockIdx.x;
    int b = r >> 5, s = r & 31;
    int e = (int)(unsigned)(g_key[r] & 0xFFFFFFFFULL);
    int k = threadIdx.x;
    float c = cb[e*ED + k];
    float z = g_z[b*FLAT_Z + k*32 + s];
    g_zq[b*FLAT_Z + k*32 + s] = c;
    float d = c - z; d = d * d;
    #pragma unroll
    for (int off = 16; off; off >>= 1) d += __shfl_down_sync(0xffffffffu, d, off);
    __shared__ float red[4];
    if ((threadIdx.x & 31) == 0) red[threadIdx.x >> 5] = d;
    __syncthreads();
    if (threadIdx.x == 0) g_losspart[r] = red[0]+red[1]+red[2]+red[3];
}

// pack zq into single fp16x2 [k2][batch] words
__global__ void __launch_bounds__(256) z_pack_k()
{
    int b = blockIdx.x;
    for (int w = threadIdx.x; w < FLAT_Z/2; w += 256){
        float f0 = g_zq[b*FLAT_Z + 2*w];
        float f1 = g_zq[b*FLAT_Z + 2*w + 1];
        g_zpk[(size_t)w*BB + b] = packh(f0, f1);
    }
}

__global__ void __launch_bounds__(256) loss_reduce_k(float* __restrict__ dst)
{
    float s = 0.f;
    for (int i = threadIdx.x; i < NROWS; i += 256) s += g_losspart[i];
    __shared__ float rs[256];
    rs[threadIdx.x] = s;
    __syncthreads();
    for (int off = 128; off; off >>= 1){
        if (threadIdx.x < off) rs[threadIdx.x] += rs[threadIdx.x+off];
        __syncthreads();
    }
    if (threadIdx.x == 0) *dst = rs[0] * (1.25f / (float)(BB*FLAT_Z));
}

// ---------------- launcher ----------------
extern "C" void kernel_launch(void* const* d_in, const int* in_sizes, int n_in,
                              void* d_out, int out_size)
{
    (void)in_sizes; (void)n_in;
    const float* x   = (const float*)d_in[0];
    const float* ciw = (const float*)d_in[1];
    const float* cib = (const float*)d_in[2];
    const float* lnw = (const float*)d_in[3];
    const float* lnb = (const float*)d_in[4];
    const float* miw = (const float*)d_in[5];
    const float* mib = (const float*)d_in[6];
    const float* cbk = (const float*)d_in[7];
    const float* mow = (const float*)d_in[8];
    const float* mob = (const float*)d_in[9];
    const float* cow = (const float*)d_in[10];
    const float* cob = (const float*)d_in[11];
    float* out = (float*)d_out;

    float *zp_p, *z_p, *hout_p, *himg_p;
    u32 *aph_p, *apl_p, *zpk_p;
    cudaGetSymbolAddress((void**)&zp_p,   g_zp);
    cudaGetSymbolAddress((void**)&z_p,    g_z);
    cudaGetSymbolAddress((void**)&hout_p, g_hout);
    cudaGetSymbolAddress((void**)&himg_p, g_himg);
    cudaGetSymbolAddress((void**)&aph_p,  g_aph);
    cudaGetSymbolAddress((void**)&apl_p,  g_apl);
    cudaGetSymbolAddress((void**)&zpk_p,  g_zpk);

    cudaFuncSetAttribute(mlp_mma_ws_k, cudaFuncAttributeMaxDynamicSharedMemorySize, WS_SMEM);
    cudaFuncSetAttribute(mlp_mma2_k,   cudaFuncAttributeMaxDynamicSharedMemorySize, MMA2_SMEM);
    cudaFuncSetAttribute(conv_mma_k<1>, cudaFuncAttributeMaxDynamicSharedMemorySize, MMA_SMEM);
    cudaFuncSetAttribute(conv_mma_k<2>, cudaFuncAttributeMaxDynamicSharedMemorySize, MMA_SMEM);

    // conv_in: 256 n-tiles x 1 j-tile; X = silu(x), K=256
    conv_mma_k<1><<<dim3(256, 1), 256, MMA_SMEM>>>(x, x, 4096, C_IN*SP, C_IN*SP,
                                                   ciw, cib, nullptr, C_IN);

    ln_stats_k<<<64, 256>>>();
    ln_norm_k<<<dim3(64, 16), 256>>>(lnw, lnb);

    // mlp_in: warp-specialized, 32 j-tiles x split-K 4 -> 128 CTAs (1/SM, single wave)
    mlp_mma_ws_k<<<dim3(FLAT_Z/128, 4), 384, WS_SMEM>>>(aph_p, apl_p, miw, zp_p,
                                                        FLAT_PH, FLAT_Z, FLAT_PH/4);
    combine_k<<<BB*FLAT_Z/4/256, 256>>>(zp_p, z_p, mib, 4, BB*FLAT_Z, FLAT_Z);

    cnorm_k<<<NE/256, 256>>>(cbk);
    vq_gemm_k<<<dim3(NROWS/64, NE/128), 256>>>(cbk);
    vq_gather_k<<<NROWS, 128>>>(cbk);
    z_pack_k<<<BB, 256>>>();

    // mlp_out: 128 j-tiles x split-K 2 -> 256 CTAs (fp16 x2)
    mlp_mma2_k<<<dim3(FLAT_PH/128, 2), 256, MMA2_SMEM>>>(zpk_p, mow, zp_p,
                                                         FLAT_Z, FLAT_PH, FLAT_Z/2);
    combine_k<<<BB*FLAT_PH/4/256, 256>>>(zp_p, hout_p, mob, 2, BB*FLAT_PH, FLAT_PH);

    // conv_out: 256 n-tiles x 2 j-tiles; X = silu(concat(hout, himg)), K=128
    conv_mma_k<2><<<dim3(256, 2), 256, MMA_SMEM>>>(hout_p, himg_p, NPH, FLAT_PH, FLAT_PH,
                                                   cow, cob, out, CH);

    if (out_size > OUT_ELEMS)
        loss_reduce_k<<<1, 256>>>(out + out_size - 1);
}

// round 16
// speedup vs baseline: 1.1305x; 1.1305x over previous
#include <cuda_runtime.h>
#include <cuda_bf16.h>
#include <cuda_fp16.h>
#include <cstdint>

// ---------------- constants ----------------
#define BB 64
#define C_IN 256
#define CH 128
#define NPH 64
#define SP 256          // R*R spatial
#define ED 128
#define NE 1024
#define C_OUT 256
#define FLAT_PH 16384   // NPH*R*R
#define FLAT_Z 4096     // ED*CB*NL
#define NROWS 2048      // B*CB*NL
#define OUT_ELEMS (BB*C_OUT*SP)   // 4194304

typedef unsigned long long u64;
typedef unsigned int u32;

#define DINLINE __device__ __forceinline__

DINLINE u64 pack2(float lo, float hi){ u64 r; asm("mov.b64 %0, {%1,%2};" : "=l"(r) : "f"(lo), "f"(hi)); return r; }
DINLINE void unpack2(u64 v, float &lo, float &hi){ asm("mov.b64 {%0,%1}, %2;" : "=f"(lo), "=f"(hi) : "l"(v)); }
DINLINE u64 fma2(u64 a, u64 b, u64 c){ u64 d; asm("fma.rn.f32x2 %0, %1, %2, %3;" : "=l"(d) : "l"(a), "l"(b), "l"(c)); return d; }
DINLINE float silu_f(float x){ return x / (1.f + __expf(-x)); }

// ---- fast bf16 split: h = bf16x2(x,y), l = bf16x2(residuals); 6 instrs ----
DINLINE void split2(float x, float y, u32 &h, u32 &l){
    asm("cvt.rn.bf16x2.f32 %0, %1, %2;" : "=r"(h) : "f"(y), "f"(x));   // hi=y, lo=x
    float xh = __uint_as_float(h << 16);
    float yh = __uint_as_float(h & 0xFFFF0000u);
    float rx = x - xh, ry = y - yh;
    asm("cvt.rn.bf16x2.f32 %0, %1, %2;" : "=r"(l) : "f"(ry), "f"(rx));
}

// ---- fp16 pack / split ----
DINLINE u32 packh(float x, float y){
    u32 r; asm("cvt.rn.f16x2.f32 %0, %1, %2;" : "=r"(r) : "f"(y), "f"(x)); return r;
}
DINLINE void split2h(float x, float y, u32 &h, u32 &l){
    h = packh(x, y);
    float xh, yh;
    asm("{.reg .b16 lo, hi; mov.b32 {lo, hi}, %2; cvt.f32.f16 %0, lo; cvt.f32.f16 %1, hi;}"
        : "=f"(xh), "=f"(yh) : "r"(h));
    l = packh(x - xh, y - yh);
}

DINLINE uint32_t smem_u32(const void* p){
    uint32_t a;
    asm("{ .reg .u64 t; cvta.to.shared.u64 t, %1; cvt.u32.u64 %0, t; }" : "=r"(a) : "l"(p));
    return a;
}
DINLINE void sts64(uint32_t addr, u32 a, u32 b){
    asm volatile("st.shared.v2.b32 [%0], {%1,%2};" :: "r"(addr), "r"(a), "r"(b) : "memory");
}
DINLINE void sts128q(uint32_t addr, u32 a, u32 b, u32 c, u32 d){
    asm volatile("st.shared.v4.b32 [%0], {%1,%2,%3,%4};" :: "r"(addr), "r"(a), "r"(b), "r"(c), "r"(d) : "memory");
}
DINLINE u32 lds32(uint32_t addr){
    u32 v; asm volatile("ld.shared.b32 %0, [%1];" : "=r"(v) : "r"(addr)); return v;
}
DINLINE void ldsm4(u32 (&r)[4], uint32_t addr){
    asm volatile("ldmatrix.sync.aligned.m8n8.x4.shared.b16 {%0,%1,%2,%3}, [%4];"
                 : "=r"(r[0]), "=r"(r[1]), "=r"(r[2]), "=r"(r[3]) : "r"(addr));
}
DINLINE void mma_bf16(float (&d)[4], const u32 (&a)[4], const u32 (&b)[2]){
    asm volatile("mma.sync.aligned.m16n8k16.row.col.f32.bf16.bf16.f32 "
                 "{%0,%1,%2,%3}, {%4,%5,%6,%7}, {%8,%9}, {%0,%1,%2,%3};"
                 : "+f"(d[0]), "+f"(d[1]), "+f"(d[2]), "+f"(d[3])
                 : "r"(a[0]), "r"(a[1]), "r"(a[2]), "r"(a[3]), "r"(b[0]), "r"(b[1]));
}
DINLINE void mma_f16(float (&d)[4], const u32 (&a)[4], const u32 (&b)[2]){
    asm volatile("mma.sync.aligned.m16n8k16.row.col.f32.f16.f16.f32 "
                 "{%0,%1,%2,%3}, {%4,%5,%6,%7}, {%8,%9}, {%0,%1,%2,%3};"
                 : "+f"(d[0]), "+f"(d[1]), "+f"(d[2]), "+f"(d[3])
                 : "r"(a[0]), "r"(a[1]), "r"(a[2]), "r"(a[3]), "r"(b[0]), "r"(b[1]));
}
DINLINE void cp_async16(uint32_t dst, const void* src){
    asm volatile("cp.async.cg.shared.global [%0], [%1], 16;" :: "r"(dst), "l"(src) : "memory");
}
#define CP_COMMIT() asm volatile("cp.async.commit_group;" ::: "memory")
#define CP_WAIT0()  asm volatile("cp.async.wait_group 0;" ::: "memory")

// ---------------- scratch (device globals; no allocs) ----------------
__device__ float g_hphylo[BB*FLAT_PH];   // conv_in phylo half (pre-LN)
__device__ float g_himg  [BB*FLAT_PH];   // conv_in img half (raw)
__device__ float g_stats [BB*2];         // mu, rstd per batch
__device__ float g_zp    [8*BB*FLAT_Z];  // split-K partials (8MB, shared by both MLPs)
__device__ float g_z     [BB*FLAT_Z];    // z
__device__ float g_zq    [BB*FLAT_Z];    // quantized z (fp32)
__device__ float g_cnorm [NE];           // |codebook_e|^2
__device__ u64   g_key   [NROWS];        // packed (sortable_dist<<32)|idx
__device__ float g_losspart[NROWS];
// packed activations: word w at [k2][batch]
__device__ u32   g_aph[(FLAT_PH/2)*BB];  // hn bf16 hi
__device__ u32   g_apl[(FLAT_PH/2)*BB];  // hn bf16 lo
__device__ u32   g_zpk[(FLAT_Z/2)*BB];   // zq fp16x2 (single precision term)

// ---------------- layernorm stats ----------------
__global__ void __launch_bounds__(256) ln_stats_k()
{
    int b = blockIdx.x;
    const float4* p = (const float4*)(g_hphylo + b*FLAT_PH);
    float s = 0.f, s2 = 0.f;
    for (int i = threadIdx.x; i < FLAT_PH/4; i += 256){
        float4 v = p[i];
        s  += v.x + v.y + v.z + v.w;
        s2 += v.x*v.x + v.y*v.y + v.z*v.z + v.w*v.w;
    }
    __shared__ float rs[256], rq[256];
    rs[threadIdx.x] = s; rq[threadIdx.x] = s2;
    __syncthreads();
    for (int off = 128; off; off >>= 1){
        if (threadIdx.x < off){ rs[threadIdx.x]+=rs[threadIdx.x+off]; rq[threadIdx.x]+=rq[threadIdx.x+off]; }
        __syncthreads();
    }
    if (threadIdx.x == 0){
        float mu = rs[0] * (1.f/FLAT_PH);
        float var = rq[0] * (1.f/FLAT_PH) - mu*mu;
        g_stats[b*2+0] = mu;
        g_stats[b*2+1] = rsqrtf(var + 1e-5f);
    }
}

// layernorm apply + bf16 hi/lo pack -> g_aph/g_apl ([k2][batch] layout)
__global__ void __launch_bounds__(256) ln_norm_k(const float* __restrict__ lnw,
                                                 const float* __restrict__ lnb)
{
    int b = blockIdx.x;
    int base = blockIdx.y * 1024 + threadIdx.x * 4;
    float mu = g_stats[b*2+0], rstd = g_stats[b*2+1];
    float4 v = *(const float4*)(g_hphylo + b*FLAT_PH + base);
    float4 w = *(const float4*)(lnw + base);
    float4 bb = *(const float4*)(lnb + base);
    float o0 = (v.x-mu)*rstd*w.x + bb.x;
    float o1 = (v.y-mu)*rstd*w.y + bb.y;
    float o2 = (v.z-mu)*rstd*w.z + bb.z;
    float o3 = (v.w-mu)*rstd*w.w + bb.w;
    u32 h0,l0,h1,l1;
    split2(o0,o1,h0,l0);
    split2(o2,o3,h1,l1);
    int k2 = base >> 1;
    g_aph[(size_t)k2*BB + b]     = h0;
    g_aph[(size_t)(k2+1)*BB + b] = h1;
    g_apl[(size_t)k2*BB + b]     = l0;
    g_apl[(size_t)(k2+1)*BB + b] = l1;
}

// ---------------- mma.sync bf16x3 MLP GEMM (mlp_in; R13 proven config) ----------------
// smem: Wh[128][40]b16 @0 (10240) | Wl @10240 | Ah[16][72]u32 @20480 | Al @25088; BUF=29696
#define MMA_BUF 29696
#define MMA_SMEM (2*MMA_BUF)

__global__ void __launch_bounds__(256, 2)
mlp_mma_k(const u32* __restrict__ Aph, const u32* __restrict__ Apl,
          const float* __restrict__ W, float* __restrict__ C,
          int K, int N, int kchunk)
{
    extern __shared__ char dsm[];
    uint32_t sb = smem_u32(dsm);

    int tid = threadIdx.x;
    int lane = tid & 31, wid = tid >> 5;
    int g = lane >> 2, tig = lane & 3;
    int jw = (wid & 3) * 32, bw = (wid >> 2) * 32;
    int jbase = blockIdx.x * 128;
    int k0 = blockIdx.y * kchunk;
    float* Cout = C + (size_t)blockIdx.y * 64 * N;

    float dacc[2][4][4];
    #pragma unroll
    for (int m=0;m<2;m++)
        #pragma unroll
        for (int n=0;n<4;n++)
            #pragma unroll
            for (int q=0;q<4;q++) dacc[m][n][q] = 0.f;

    const int nch = kchunk >> 5;
    int k2t = tid >> 4, b4 = (tid & 15) * 4;
    uint32_t aoff = (u32)(k2t*72 + b4)*4;

    float4 wreg[4];

    {
        int kbase = k0 >> 1;
        cp_async16(sb + 20480 + aoff, Aph + (size_t)(kbase + k2t)*BB + b4);
        cp_async16(sb + 25088 + aoff, Apl + (size_t)(kbase + k2t)*BB + b4);
        CP_COMMIT();
    }
    #pragma unroll
    for (int i=0;i<4;i++){ int idx=tid+256*i; int r=idx>>3, s=idx&7;
        wreg[i] = *(const float4*)(W + (size_t)(jbase+r)*K + k0 + s*4); }
    #pragma unroll
    for (int i=0;i<4;i++){ int idx=tid+256*i; int r=idx>>3, s=idx&7;
        u32 h0,l0,h1,l1;
        split2(wreg[i].x, wreg[i].y, h0, l0);
        split2(wreg[i].z, wreg[i].w, h1, l1);
        uint32_t off = r*80 + s*8;
        sts64(sb + off, h0, h1);
        sts64(sb + 10240 + off, l0, l1);
    }
    CP_WAIT0();
    __syncthreads();

    for (int ch = 0; ch < nch; ch++){
        int cur = ch & 1;
        bool more = (ch+1) < nch;
        if (more){
            int kk = k0 + (ch+1)*32;
            uint32_t Bn = sb + (cur^1)*MMA_BUF;
            int kbase = kk >> 1;
            cp_async16(Bn + 20480 + aoff, Aph + (size_t)(kbase + k2t)*BB + b4);
            cp_async16(Bn + 25088 + aoff, Apl + (size_t)(kbase + k2t)*BB + b4);
            CP_COMMIT();
            #pragma unroll
            for (int i=0;i<4;i++){ int idx=tid+256*i; int r=idx>>3, s=idx&7;
                wreg[i] = *(const float4*)(W + (size_t)(jbase+r)*K + kk + s*4); }
        }

        // compute on buffer cur: preload ALL fragments, then mma block
        {
            uint32_t Bb = sb + cur*MMA_BUF;
            int lrow = ((lane>>3)&1)*8 + (lane&7);
            int lkc  = (lane>>4)*8;
            u32 wh[2][2][4], wl[2][2][4];
            #pragma unroll
            for (int ks = 0; ks < 2; ks++)
                #pragma unroll
                for (int m=0;m<2;m++){
                    uint32_t ad = Bb + (u32)((jw + m*16 + lrow)*40 + lkc + ks*16)*2;
                    ldsm4(wh[ks][m], ad);
                    ldsm4(wl[ks][m], ad + 10240);
                }
            u32 bh[2][4][2], bl[2][4][2];
            #pragma unroll
            for (int ks = 0; ks < 2; ks++)
                #pragma unroll
                for (int nf=0;nf<4;nf++){
                    uint32_t a0 = Bb + 20480 + (u32)((ks*8+tig)*72 + bw + nf*8 + g)*4;
                    bh[ks][nf][0] = lds32(a0);
                    bh[ks][nf][1] = lds32(a0 + 4*72*4);
                    bl[ks][nf][0] = lds32(a0 + 4608);
                    bl[ks][nf][1] = lds32(a0 + 4608 + 4*72*4);
                }
            #pragma unroll
            for (int ks = 0; ks < 2; ks++)
                #pragma unroll
                for (int m=0;m<2;m++)
                    #pragma unroll
                    for (int nf=0;nf<4;nf++){
                        mma_bf16(dacc[m][nf], wh[ks][m], bh[ks][nf]);
                        mma_bf16(dacc[m][nf], wh[ks][m], bl[ks][nf]);
                        mma_bf16(dacc[m][nf], wl[ks][m], bh[ks][nf]);
                    }
        }

        if (more){
            uint32_t Bn = sb + (cur^1)*MMA_BUF;
            #pragma unroll
            for (int i=0;i<4;i++){ int idx=tid+256*i; int r=idx>>3, s=idx&7;
                u32 h0,l0,h1,l1;
                split2(wreg[i].x, wreg[i].y, h0, l0);
                split2(wreg[i].z, wreg[i].w, h1, l1);
                uint32_t off = r*80 + s*8;
                sts64(Bn + off, h0, h1);
                sts64(Bn + 10240 + off, l0, l1);
            }
        }
        CP_WAIT0();
        __syncthreads();
    }

    #pragma unroll
    for (int m=0;m<2;m++){
        int j = jbase + jw + m*16 + g;
        #pragma unroll
        for (int nf=0;nf<4;nf++){
            int b = bw + nf*8 + 2*tig;
            Cout[(size_t)b*N + j]         = dacc[m][nf][0];
            Cout[(size_t)(b+1)*N + j]     = dacc[m][nf][1];
            Cout[(size_t)b*N + j + 8]     = dacc[m][nf][2];
            Cout[(size_t)(b+1)*N + j + 8] = dacc[m][nf][3];
        }
    }
}

// ---------------- mma.sync fp16x2 MLP GEMM (mlp_out; 2 passes, R13 config) ----------------
// smem: Wh[128][40]b16 @0 (10240) | Wl @10240 | A[16][72]u32 @20480 (4608); BUF2=25088
#define MMA2_BUF 25088
#define MMA2_SMEM (2*MMA2_BUF)

__global__ void __launch_bounds__(256, 2)
mlp_mma2_k(const u32* __restrict__ Apk,
           const float* __restrict__ W, float* __restrict__ C,
           int K, int N, int kchunk)
{
    extern __shared__ char dsm[];
    uint32_t sb = smem_u32(dsm);

    int tid = threadIdx.x;
    int lane = tid & 31, wid = tid >> 5;
    int g = lane >> 2, tig = lane & 3;
    int jw = (wid & 3) * 32, bw = (wid >> 2) * 32;
    int jbase = blockIdx.x * 128;
    int k0 = blockIdx.y * kchunk;
    float* Cout = C + (size_t)blockIdx.y * 64 * N;

    float dacc[2][4][4];
    #pragma unroll
    for (int m=0;m<2;m++)
        #pragma unroll
        for (int n=0;n<4;n++)
            #pragma unroll
            for (int q=0;q<4;q++) dacc[m][n][q] = 0.f;

    const int nch = kchunk >> 5;
    int k2t = tid >> 4, b4 = (tid & 15) * 4;
    uint32_t aoff = (u32)(k2t*72 + b4)*4;

    float4 wreg[4];

    {
        int kbase = k0 >> 1;
        cp_async16(sb + 20480 + aoff, Apk + (size_t)(kbase + k2t)*BB + b4);
        CP_COMMIT();
    }
    #pragma unroll
    for (int i=0;i<4;i++){ int idx=tid+256*i; int r=idx>>3, s=idx&7;
        wreg[i] = *(const float4*)(W + (size_t)(jbase+r)*K + k0 + s*4); }
    #pragma unroll
    for (int i=0;i<4;i++){ int idx=tid+256*i; int r=idx>>3, s=idx&7;
        u32 h0,l0,h1,l1;
        split2h(wreg[i].x, wreg[i].y, h0, l0);
        split2h(wreg[i].z, wreg[i].w, h1, l1);
        uint32_t off = r*80 + s*8;
        sts64(sb + off, h0, h1);
        sts64(sb + 10240 + off, l0, l1);
    }
    CP_WAIT0();
    __syncthreads();

    for (int ch = 0; ch < nch; ch++){
        int cur = ch & 1;
        bool more = (ch+1) < nch;
        if (more){
            int kk = k0 + (ch+1)*32;
            uint32_t Bn = sb + (cur^1)*MMA2_BUF;
            int kbase = kk >> 1;
            cp_async16(Bn + 20480 + aoff, Apk + (size_t)(kbase + k2t)*BB + b4);
            CP_COMMIT();
            #pragma unroll
            for (int i=0;i<4;i++){ int idx=tid+256*i; int r=idx>>3, s=idx&7;
                wreg[i] = *(const float4*)(W + (size_t)(jbase+r)*K + kk + s*4); }
        }

        {
            uint32_t Bb = sb + cur*MMA2_BUF;
            int lrow = ((lane>>3)&1)*8 + (lane&7);
            int lkc  = (lane>>4)*8;
            #pragma unroll
            for (int ks = 0; ks < 2; ks++){
                u32 wh[2][4], wl[2][4];
                #pragma unroll
                for (int m=0;m<2;m++){
                    uint32_t ad = Bb + (u32)((jw + m*16 + lrow)*40 + lkc + ks*16)*2;
                    ldsm4(wh[m], ad);
                    ldsm4(wl[m], ad + 10240);
                }
                u32 bh[4][2];
                #pragma unroll
                for (int nf=0;nf<4;nf++){
                    uint32_t a0 = Bb + 20480 + (u32)((ks*8+tig)*72 + bw + nf*8 + g)*4;
                    bh[nf][0] = lds32(a0);
                    bh[nf][1] = lds32(a0 + 4*72*4);
                }
                #pragma unroll
                for (int m=0;m<2;m++)
                    #pragma unroll
                    for (int nf=0;nf<4;nf++){
                        mma_f16(dacc[m][nf], wh[m], bh[nf]);
                        mma_f16(dacc[m][nf], wl[m], bh[nf]);
                    }
            }
        }

        if (more){
            uint32_t Bn = sb + (cur^1)*MMA2_BUF;
            #pragma unroll
            for (int i=0;i<4;i++){ int idx=tid+256*i; int r=idx>>3, s=idx&7;
                u32 h0,l0,h1,l1;
                split2h(wreg[i].x, wreg[i].y, h0, l0);
                split2h(wreg[i].z, wreg[i].w, h1, l1);
                uint32_t off = r*80 + s*8;
                sts64(Bn + off, h0, h1);
                sts64(Bn + 10240 + off, l0, l1);
            }
        }
        CP_WAIT0();
        __syncthreads();
    }

    #pragma unroll
    for (int m=0;m<2;m++){
        int j = jbase + jw + m*16 + g;
        #pragma unroll
        for (int nf=0;nf<4;nf++){
            int b = bw + nf*8 + 2*tig;
            Cout[(size_t)b*N + j]         = dacc[m][nf][0];
            Cout[(size_t)(b+1)*N + j]     = dacc[m][nf][1];
            Cout[(size_t)b*N + j + 8]     = dacc[m][nf][2];
            Cout[(size_t)(b+1)*N + j + 8] = dacc[m][nf][3];
        }
    }
}

// ---------------- mma.sync bf16x3 CONV_IN GEMM (unchanged, proven) ----------------
__global__ void __launch_bounds__(256, 2)
conv_in_mma_k(const float* __restrict__ x,
              const float* __restrict__ W, const float* __restrict__ bias,
              int K)
{
    extern __shared__ char dsm[];
    uint32_t sb = smem_u32(dsm);

    int tid = threadIdx.x;
    int lane = tid & 31, wid = tid >> 5;
    int g = lane >> 2, tig = lane & 3;
    int jw = (wid & 3) * 32, bw = (wid >> 2) * 32;
    int jbase = 0;
    int nbase = blockIdx.x * 64;
    int b = nbase >> 8, pbase = nbase & 255;

    float dacc[2][4][4];
    #pragma unroll
    for (int m=0;m<2;m++)
        #pragma unroll
        for (int n=0;n<4;n++)
            #pragma unroll
            for (int q=0;q<4;q++) dacc[m][n][q] = 0.f;

    const int nch = K >> 5;
    int c2t = tid >> 4, p4 = tid & 15;

    float4 wreg[4], bf0, bf1;

    #pragma unroll
    for (int i=0;i<4;i++){ int idx=tid+256*i; int r=idx>>3, s=idx&7;
        wreg[i] = *(const float4*)(W + (size_t)(jbase+r)*K + s*4); }
    {
        int c = 2*c2t;
        const float* s0 = x + (size_t)b*(C_IN*SP) + c*256;
        bf0 = *(const float4*)(s0 + pbase + p4*4);
        bf1 = *(const float4*)(s0 + 256 + pbase + p4*4);
    }
    {
        uint32_t Bb = sb;
        #pragma unroll
        for (int i=0;i<4;i++){ int idx=tid+256*i; int r=idx>>3, s=idx&7;
            u32 h0,l0,h1,l1;
            split2(wreg[i].x, wreg[i].y, h0, l0);
            split2(wreg[i].z, wreg[i].w, h1, l1);
            uint32_t off = r*80 + s*8;
            sts64(Bb + off, h0, h1);
            sts64(Bb + 10240 + off, l0, l1);
        }
        u32 h[4], l[4];
        split2(silu_f(bf0.x), silu_f(bf1.x), h[0], l[0]);
        split2(silu_f(bf0.y), silu_f(bf1.y), h[1], l[1]);
        split2(silu_f(bf0.z), silu_f(bf1.z), h[2], l[2]);
        split2(silu_f(bf0.w), silu_f(bf1.w), h[3], l[3]);
        uint32_t off = (u32)(c2t*72 + p4*4)*4;
        sts128q(Bb + 20480 + off, h[0], h[1], h[2], h[3]);
        sts128q(Bb + 25088 + off, l[0], l[1], l[2], l[3]);
    }
    __syncthreads();

    for (int ch = 0; ch < nch; ch++){
        int cur = ch & 1;
        bool more = (ch+1) < nch;
        if (more){
            int kk = (ch+1)*32;
            #pragma unroll
            for (int i=0;i<4;i++){ int idx=tid+256*i; int r=idx>>3, s=idx&7;
                wreg[i] = *(const float4*)(W + (size_t)(jbase+r)*K + kk + s*4); }
            int c = kk + 2*c2t;
            const float* s0 = x + (size_t)b*(C_IN*SP) + c*256;
            bf0 = *(const float4*)(s0 + pbase + p4*4);
            bf1 = *(const float4*)(s0 + 256 + pbase + p4*4);
        }

        {
            uint32_t Bb = sb + cur*MMA_BUF;
            int lrow = ((lane>>3)&1)*8 + (lane&7);
            int lkc  = (lane>>4)*8;
            #pragma unroll
            for (int ks = 0; ks < 2; ks++){
                u32 wh[2][4], wl[2][4];
                #pragma unroll
                for (int m=0;m<2;m++){
                    uint32_t ad = Bb + (u32)((jw + m*16 + lrow)*40 + lkc + ks*16)*2;
                    ldsm4(wh[m], ad);
                    ldsm4(wl[m], ad + 10240);
                }
                u32 bh[4][2], bl[4][2];
                #pragma unroll
                for (int nf=0;nf<4;nf++){
                    uint32_t a0 = Bb + 20480 + (u32)((ks*8+tig)*72 + bw + nf*8 + g)*4;
                    bh[nf][0] = lds32(a0);
                    bh[nf][1] = lds32(a0 + 4*72*4);
                    bl[nf][0] = lds32(a0 + 4608);
                    bl[nf][1] = lds32(a0 + 4608 + 4*72*4);
                }
                #pragma unroll
                for (int m=0;m<2;m++)
                    #pragma unroll
                    for (int nf=0;nf<4;nf++){
                        mma_bf16(dacc[m][nf], wh[m], bh[nf]);
                        mma_bf16(dacc[m][nf], wh[m], bl[nf]);
                        mma_bf16(dacc[m][nf], wl[m], bh[nf]);
                    }
            }
        }

        if (more){
            uint32_t Bb = sb + (cur^1)*MMA_BUF;
            #pragma unroll
            for (int i=0;i<4;i++){ int idx=tid+256*i; int r=idx>>3, s=idx&7;
                u32 h0,l0,h1,l1;
                split2(wreg[i].x, wreg[i].y, h0, l0);
                split2(wreg[i].z, wreg[i].w, h1, l1);
                uint32_t off = r*80 + s*8;
                sts64(Bb + off, h0, h1);
                sts64(Bb + 10240 + off, l0, l1);
            }
            u32 h[4], l[4];
            split2(silu_f(bf0.x), silu_f(bf1.x), h[0], l[0]);
            split2(silu_f(bf0.y), silu_f(bf1.y), h[1], l[1]);
            split2(silu_f(bf0.z), silu_f(bf1.z), h[2], l[2]);
            split2(silu_f(bf0.w), silu_f(bf1.w), h[3], l[3]);
            uint32_t off = (u32)(c2t*72 + p4*4)*4;
            sts128q(Bb + 20480 + off, h[0], h[1], h[2], h[3]);
            sts128q(Bb + 25088 + off, l[0], l[1], l[2], l[3]);
        }
        __syncthreads();
    }

    #pragma unroll
    for (int m=0;m<2;m++){
        int j = jw + m*16 + g;
        float b0v = bias[j], b1v = bias[j+8];
        #pragma unroll
        for (int nf=0;nf<4;nf++){
            int p = pbase + bw + nf*8 + 2*tig;
            float v0 = dacc[m][nf][0] + b0v, v1 = dacc[m][nf][1] + b0v;
            float v2 = dacc[m][nf][2] + b1v, v3 = dacc[m][nf][3] + b1v;
            float* d0 = (j < NPH) ? (g_hphylo + (size_t)b*FLAT_PH + j*256 + p)
                                  : (g_himg   + (size_t)b*FLAT_PH + (j-NPH)*256 + p);
            *(float2*)d0          = make_float2(v0, v1);
            *(float2*)(d0 + 2048) = make_float2(v2, v3);
        }
    }
}

// ---------------- fp16x2 CONV_OUT GEMM: fuses mlp_out combine+bias+silu ----------------
// X[c][n]: c<NPH -> silu(zpP0 + zpP1 + mlp_out_bias); c>=NPH -> silu(himg).
// smem layout = MMA2 (Wh|Wl|A fp16 single).
__global__ void __launch_bounds__(256, 2)
conv_out_mma_k(const float* __restrict__ zpP,     // split-K partials of mlp_out (2 slabs)
               const float* __restrict__ mob,     // mlp_out bias [FLAT_PH]
               const float* __restrict__ himg,
               const float* __restrict__ W, const float* __restrict__ bias,
               float* __restrict__ out, int K)
{
    extern __shared__ char dsm[];
    uint32_t sb = smem_u32(dsm);

    int tid = threadIdx.x;
    int lane = tid & 31, wid = tid >> 5;
    int g = lane >> 2, tig = lane & 3;
    int jw = (wid & 3) * 32, bw = (wid >> 2) * 32;
    int jbase = blockIdx.y * 128;
    int nbase = blockIdx.x * 64;
    int b = nbase >> 8, pbase = nbase & 255;

    float dacc[2][4][4];
    #pragma unroll
    for (int m=0;m<2;m++)
        #pragma unroll
        for (int n=0;n<4;n++)
            #pragma unroll
            for (int q=0;q<4;q++) dacc[m][n][q] = 0.f;

    const int nch = K >> 5;
    int c2t = tid >> 4, p4 = tid & 15;

    float4 wreg[4], bf0, bf1;

    // row loader: returns pre-silu activation row values
    auto load_row = [&](int cc) -> float4 {
        int off = cc < NPH ? cc*256 : (cc-NPH)*256;
        if (cc < NPH){
            const float* p0 = zpP + (size_t)b*FLAT_PH + off + pbase + p4*4;
            float4 a = *(const float4*)p0;
            float4 c = *(const float4*)(p0 + (size_t)64*FLAT_PH);
            float4 d = *(const float4*)(mob + off + pbase + p4*4);
            float4 r; r.x=a.x+c.x+d.x; r.y=a.y+c.y+d.y; r.z=a.z+c.z+d.z; r.w=a.w+c.w+d.w;
            return r;
        } else {
            return *(const float4*)(himg + (size_t)b*FLAT_PH + off + pbase + p4*4);
        }
    };

    #pragma unroll
    for (int i=0;i<4;i++){ int idx=tid+256*i; int r=idx>>3, s=idx&7;
        wreg[i] = *(const float4*)(W + (size_t)(jbase+r)*K + s*4); }
    {
        int c = 2*c2t;
        bf0 = load_row(c);
        bf1 = load_row(c+1);
    }
    {
        uint32_t Bb = sb;
        #pragma unroll
        for (int i=0;i<4;i++){ int idx=tid+256*i; int r=idx>>3, s=idx&7;
            u32 h0,l0,h1,l1;
            split2h(wreg[i].x, wreg[i].y, h0, l0);
            split2h(wreg[i].z, wreg[i].w, h1, l1);
            uint32_t off = r*80 + s*8;
            sts64(Bb + off, h0, h1);
            sts64(Bb + 10240 + off, l0, l1);
        }
        u32 h[4];
        h[0] = packh(silu_f(bf0.x), silu_f(bf1.x));
        h[1] = packh(silu_f(bf0.y), silu_f(bf1.y));
        h[2] = packh(silu_f(bf0.z), silu_f(bf1.z));
        h[3] = packh(silu_f(bf0.w), silu_f(bf1.w));
        uint32_t off = (u32)(c2t*72 + p4*4)*4;
        sts128q(Bb + 20480 + off, h[0], h[1], h[2], h[3]);
    }
    __syncthreads();

    for (int ch = 0; ch < nch; ch++){
        int cur = ch & 1;
        bool more = (ch+1) < nch;
        if (more){
            int kk = (ch+1)*32;
            #pragma unroll
            for (int i=0;i<4;i++){ int idx=tid+256*i; int r=idx>>3, s=idx&7;
                wreg[i] = *(const float4*)(W + (size_t)(jbase+r)*K + kk + s*4); }
            int c = kk + 2*c2t;
            bf0 = load_row(c);
            bf1 = load_row(c+1);
        }

        {
            uint32_t Bb = sb + cur*MMA2_BUF;
            int lrow = ((lane>>3)&1)*8 + (lane&7);
            int lkc  = (lane>>4)*8;
            #pragma unroll
            for (int ks = 0; ks < 2; ks++){
                u32 wh[2][4], wl[2][4];
                #pragma unroll
                for (int m=0;m<2;m++){
                    uint32_t ad = Bb + (u32)((jw + m*16 + lrow)*40 + lkc + ks*16)*2;
                    ldsm4(wh[m], ad);
                    ldsm4(wl[m], ad + 10240);
                }
                u32 bh[4][2];
                #pragma unroll
                for (int nf=0;nf<4;nf++){
                    uint32_t a0 = Bb + 20480 + (u32)((ks*8+tig)*72 + bw + nf*8 + g)*4;
                    bh[nf][0] = lds32(a0);
                    bh[nf][1] = lds32(a0 + 4*72*4);
                }
                #pragma unroll
                for (int m=0;m<2;m++)
                    #pragma unroll
                    for (int nf=0;nf<4;nf++){
                        mma_f16(dacc[m][nf], wh[m], bh[nf]);
                        mma_f16(dacc[m][nf], wl[m], bh[nf]);
                    }
            }
        }

        if (more){
            uint32_t Bb = sb + (cur^1)*MMA2_BUF;
            #pragma unroll
            for (int i=0;i<4;i++){ int idx=tid+256*i; int r=idx>>3, s=idx&7;
                u32 h0,l0,h1,l1;
                split2h(wreg[i].x, wreg[i].y, h0, l0);
                split2h(wreg[i].z, wreg[i].w, h1, l1);
                uint32_t off = r*80 + s*8;
                sts64(Bb + off, h0, h1);
                sts64(Bb + 10240 + off, l0, l1);
            }
            u32 h[4];
            h[0] = packh(silu_f(bf0.x), silu_f(bf1.x));
            h[1] = packh(silu_f(bf0.y), silu_f(bf1.y));
            h[2] = packh(silu_f(bf0.z), silu_f(bf1.z));
            h[3] = packh(silu_f(bf0.w), silu_f(bf1.w));
            uint32_t off = (u32)(c2t*72 + p4*4)*4;
            sts128q(Bb + 20480 + off, h[0], h[1], h[2], h[3]);
        }
        __syncthreads();
    }

    #pragma unroll
    for (int m=0;m<2;m++){
        int j = jbase + jw + m*16 + g;
        float b0v = bias[j], b1v = bias[j+8];
        #pragma unroll
        for (int nf=0;nf<4;nf++){
            int p = pbase + bw + nf*8 + 2*tig;
            float v0 = dacc[m][nf][0] + b0v, v1 = dacc[m][nf][1] + b0v;
            float v2 = dacc[m][nf][2] + b1v, v3 = dacc[m][nf][3] + b1v;
            float* d0 = out + (size_t)b*(C_OUT*SP) + (size_t)j*256 + p;
            *(float2*)d0          = make_float2(v0, v1);
            *(float2*)(d0 + 2048) = make_float2(v2, v3);
        }
    }
}

// ---------------- combine nsplit partials + bias (mlp_in only) ----------------
__global__ void __launch_bounds__(256) combine_k(const float* __restrict__ P,
                                                 float* __restrict__ out,
                                                 const float* __restrict__ bias,
                                                 int nsplit, int total, int N)
{
    int i = blockIdx.x * 256 + threadIdx.x;
    const float4* P4 = (const float4*)P;
    float4 s = P4[i];
    int stride = total >> 2;
    for (int sp = 1; sp < nsplit; sp++){
        float4 a = P4[i + sp*stride];
        s.x+=a.x; s.y+=a.y; s.z+=a.z; s.w+=a.w;
    }
    int j = (i * 4) & (N - 1);
    float4 bv = *(const float4*)(bias + j);
    s.x+=bv.x; s.y+=bv.y; s.z+=bv.z; s.w+=bv.w;
    ((float4*)out)[i] = s;
}

// ---------------- codebook norms + vq init (fused) ----------------
__global__ void __launch_bounds__(256) cnorm_k(const float* __restrict__ cb)
{
    int e = blockIdx.x * 256 + threadIdx.x;      // 0..1023
    const float4* r = (const float4*)(cb + e*ED);
    float s = 0.f;
    #pragma unroll 8
    for (int i = 0; i < ED/4; i++){
        float4 v = r[i];
        s += v.x*v.x + v.y*v.y + v.z*v.z + v.w*v.w;
    }
    g_cnorm[e] = s;
    g_key[2*e]   = ~0ULL;
    g_key[2*e+1] = ~0ULL;
    g_losspart[2*e]   = 0.f;
    g_losspart[2*e+1] = 0.f;
}

// ---------------- VQ distance GEMM + argmin ----------------
__global__ void __launch_bounds__(256) vq_gemm_k(const float* __restrict__ cb)
{
    int rbase = blockIdx.x * 64;
    int ebase = blockIdx.y * 128;
    int b0 = rbase >> 5;

    __shared__ float Zs[32][68];
    __shared__ float Cs[32][132];
    __shared__ float cn[128];

    int tid = threadIdx.x;
    if (tid < 128) cn[tid] = g_cnorm[ebase + tid];
    int tx = tid & 15, ty = tid >> 4;
    int r0 = ty * 4, e0 = tx * 8;

    u64 acc2[4][4];
    #pragma unroll
    for (int i=0;i<4;i++)
        #pragma unroll
        for (int j=0;j<4;j++) acc2[i][j] = pack2(0.f,0.f);

    for (int kc = 0; kc < ED; kc += 32){
        #pragma unroll
        for (int it = 0; it < 2; it++){
            int i = tid + it*256;
            int brel = i >> 8;
            int t = (i & 255) * 4;
            float4 v = *(const float4*)(g_z + (b0+brel)*FLAT_Z + kc*32 + t);
            int k = t >> 5, s = t & 31;
            *(float4*)&Zs[k][brel*32 + s] = v;
        }
        #pragma unroll
        for (int it = 0; it < 4; it++){
            int i = tid + it*256;
            int el = i >> 3; int kq = (i & 7) * 4;
            float4 v = *(const float4*)(cb + (ebase+el)*ED + kc + kq);
            Cs[kq+0][el]=v.x; Cs[kq+1][el]=v.y; Cs[kq+2][el]=v.z; Cs[kq+3][el]=v.w;
        }
        __syncthreads();
        #pragma unroll 4
        for (int k = 0; k < 32; k++){
            float4 a  = *(const float4*)&Zs[k][r0];
            float4 c0 = *(const float4*)&Cs[k][e0];
            float4 c1 = *(const float4*)&Cs[k][e0+4];
            u64 cp[4] = {pack2(c0.x,c0.y), pack2(c0.z,c0.w),
                         pack2(c1.x,c1.y), pack2(c1.z,c1.w)};
            float av[4] = {a.x,a.y,a.z,a.w};
            #pragma unroll
            for (int i=0;i<4;i++){
                u64 aa = pack2(av[i], av[i]);
                #pragma unroll
                for (int j=0;j<4;j++) acc2[i][j] = fma2(aa, cp[j], acc2[i][j]);
            }
        }
        __syncthreads();
    }

    #pragma unroll
    for (int i=0;i<4;i++){
        float best = 3.4e38f; int be = 0;
        #pragma unroll
        for (int j=0;j<4;j++){
            float d0, d1;
            unpack2(acc2[i][j], d0, d1);
            float da = cn[e0+2*j]   - 2.f*d0;
            float db = cn[e0+2*j+1] - 2.f*d1;
            if (da < best){ best = da; be = e0+2*j; }
            if (db < best){ best = db; be = e0+2*j+1; }
        }
        unsigned int bits = __float_as_uint(best);
        unsigned int key32 = (bits & 0x80000000u) ? ~bits : (bits | 0x80000000u);
        u64 key = ((u64)key32 << 32) | (unsigned)(ebase + be);
        atomicMin(&g_key[rbase + r0 + i], key);
    }
}

// ---------------- gather zq (fp32) + per-row loss partial ----------------
__global__ void __launch_bounds__(128) vq_gather_k(const float* __restrict__ cb)
{
    int r = blockIdx.x;
    int b = r >> 5, s = r & 31;
    int e = (int)(unsigned)(g_key[r] & 0xFFFFFFFFULL);
    int k = threadIdx.x;
    float c = cb[e*ED + k];
    float z = g_z[b*FLAT_Z + k*32 + s];
    g_zq[b*FLAT_Z + k*32 + s] = c;
    float d = c - z; d = d * d;
    #pragma unroll
    for (int off = 16; off; off >>= 1) d += __shfl_down_sync(0xffffffffu, d, off);
    __shared__ float red[4];
    if ((threadIdx.x & 31) == 0) red[threadIdx.x >> 5] = d;
    __syncthreads();
    if (threadIdx.x == 0) g_losspart[r] = red[0]+red[1]+red[2]+red[3];
}

// pack zq into single fp16x2 [k2][batch] words
__global__ void __launch_bounds__(256) z_pack_k()
{
    int b = blockIdx.x;
    for (int w = threadIdx.x; w < FLAT_Z/2; w += 256){
        float f0 = g_zq[b*FLAT_Z + 2*w];
        float f1 = g_zq[b*FLAT_Z + 2*w + 1];
        g_zpk[(size_t)w*BB + b] = packh(f0, f1);
    }
}

__global__ void __launch_bounds__(256) loss_reduce_k(float* __restrict__ dst)
{
    float s = 0.f;
    for (int i = threadIdx.x; i < NROWS; i += 256) s += g_losspart[i];
    __shared__ float rs[256];
    rs[threadIdx.x] = s;
    __syncthreads();
    for (int off = 128; off; off >>= 1){
        if (threadIdx.x < off) rs[threadIdx.x] += rs[threadIdx.x+off];
        __syncthreads();
    }
    if (threadIdx.x == 0) *dst = rs[0] * (1.25f / (float)(BB*FLAT_Z));
}

// ---------------- launcher ----------------
extern "C" void kernel_launch(void* const* d_in, const int* in_sizes, int n_in,
                              void* d_out, int out_size)
{
    (void)in_sizes; (void)n_in;
    const float* x   = (const float*)d_in[0];
    const float* ciw = (const float*)d_in[1];
    const float* cib = (const float*)d_in[2];
    const float* lnw = (const float*)d_in[3];
    const float* lnb = (const float*)d_in[4];
    const float* miw = (const float*)d_in[5];
    const float* mib = (const float*)d_in[6];
    const float* cbk = (const float*)d_in[7];
    const float* mow = (const float*)d_in[8];
    const float* mob = (const float*)d_in[9];
    const float* cow = (const float*)d_in[10];
    const float* cob = (const float*)d_in[11];
    float* out = (float*)d_out;

    float *zp_p, *z_p, *himg_p;
    u32 *aph_p, *apl_p, *zpk_p;
    cudaGetSymbolAddress((void**)&zp_p,   g_zp);
    cudaGetSymbolAddress((void**)&z_p,    g_z);
    cudaGetSymbolAddress((void**)&himg_p, g_himg);
    cudaGetSymbolAddress((void**)&aph_p,  g_aph);
    cudaGetSymbolAddress((void**)&apl_p,  g_apl);
    cudaGetSymbolAddress((void**)&zpk_p,  g_zpk);

    cudaFuncSetAttribute(mlp_mma_k,     cudaFuncAttributeMaxDynamicSharedMemorySize, MMA_SMEM);
    cudaFuncSetAttribute(mlp_mma2_k,    cudaFuncAttributeMaxDynamicSharedMemorySize, MMA2_SMEM);
    cudaFuncSetAttribute(conv_in_mma_k, cudaFuncAttributeMaxDynamicSharedMemorySize, MMA_SMEM);
    cudaFuncSetAttribute(conv_out_mma_k,cudaFuncAttributeMaxDynamicSharedMemorySize, MMA2_SMEM);

    // conv_in: 256 n-tiles; X = silu(x), K=256, j-tile = all 128 outputs
    conv_in_mma_k<<<256, 256, MMA_SMEM>>>(x, ciw, cib, C_IN);

    ln_stats_k<<<64, 256>>>();
    ln_norm_k<<<dim3(64, 16), 256>>>(lnw, lnb);

    // mlp_in: 32 j-tiles x split-K 8 -> 256 CTAs (bf16 x3, argmin-safe)
    mlp_mma_k<<<dim3(FLAT_Z/128, 8), 256, MMA_SMEM>>>(aph_p, apl_p, miw, zp_p,
                                                      FLAT_PH, FLAT_Z, FLAT_PH/8);
    combine_k<<<BB*FLAT_Z/4/256, 256>>>(zp_p, z_p, mib, 8, BB*FLAT_Z, FLAT_Z);

    cnorm_k<<<NE/256, 256>>>(cbk);
    vq_gemm_k<<<dim3(NROWS/64, NE/128), 256>>>(cbk);
    vq_gather_k<<<NROWS, 128>>>(cbk);
    z_pack_k<<<BB, 256>>>();

    // mlp_out: 128 j-tiles x split-K 2 -> 256 CTAs (fp16 x2); partials left in zp_p
    mlp_mma2_k<<<dim3(FLAT_PH/128, 2), 256, MMA2_SMEM>>>(zpk_p, mow, zp_p,
                                                         FLAT_Z, FLAT_PH, FLAT_Z/2);

    // conv_out (fp16x2): fuses mlp_out partial-combine + bias + silu into its loader
    conv_out_mma_k<<<dim3(256, 2), 256, MMA2_SMEM>>>(zp_p, mob, himg_p,
                                                     cow, cob, out, CH);

    if (out_size > OUT_ELEMS)
        loss_reduce_k<<<1, 256>>>(out + out_size - 1);
}